// round 5
// baseline (speedup 1.0000x reference)
#include <cuda_runtime.h>
#include <cstdint>

// Layout: MARK_AX=0, OP_MUL=1, ALU_LO=16, ALU_HI=32, AX_CARRY_LO=48, AX_CARRY_HI=64,
// OUTPUT_LO=80, OUTPUT_HI=96, BD_DIM=128. GE pos-0 input is 3-sparse:
//   h_j = relu(a*W1[0,j] + b*W1[1,j] + W1[29,j] + b1[j]),  y = sum_j h_j*W2[j,40] + b2[40]
// Coefficients packed once per launch: g_coeff[j] = (W1[0,j], W1[1,j], W1[29,j]+b1[j], W2[j,40]).
// Main kernel: 4 tokens per warp -> 4 front-batched LDG.128 per lane (MLP=4).

__device__ float4 g_coeff[256];
__device__ float  g_b2_40;

__global__ void prep_kernel(const float* __restrict__ W1,
                            const float* __restrict__ b1,
                            const float* __restrict__ W2,
                            const float* __restrict__ b2)
{
    int j = threadIdx.x;  // 256 threads
    g_coeff[j] = make_float4(W1[j],
                             W1[256 + j],
                             W1[29 * 256 + j] + b1[j],
                             W2[j * 64 + 40]);
    if (j == 0) g_b2_40 = b2[40];
}

__device__ __forceinline__ void process_active(float4& v, int lane, unsigned FULL)
{
    // argmax over four 16-elem segments: [16,32)->lanes4..7, [32,48)->8..11,
    // [48,64)->12..15, [64,80)->16..19. First-max-wins (strict >, tie -> lower idx).
    float best = v.x; int bidx = 0;
    if (v.y > best) { best = v.y; bidx = 1; }
    if (v.z > best) { best = v.z; bidx = 2; }
    if (v.w > best) { best = v.w; bidx = 3; }
    int gidx = ((lane & 3) << 2) | bidx;

    #pragma unroll
    for (int off = 1; off <= 2; off <<= 1) {
        float ob = __shfl_xor_sync(FULL, best, off);
        int   oi = __shfl_xor_sync(FULL, gidx, off);
        if (ob > best || (ob == best && oi < gidx)) { best = ob; gidx = oi; }
    }

    int a_lo = __shfl_sync(FULL, gidx, 4);
    int a_hi = __shfl_sync(FULL, gidx, 8);
    int b_lo = __shfl_sync(FULL, gidx, 12);
    int b_hi = __shfl_sync(FULL, gidx, 16);

    float fa = (float)(a_lo | (a_hi << 4));
    float fb = (float)(b_lo | (b_hi << 4));

    // MLP from packed coefficients: j = lane + 32*i -> coalesced, L1-hot (4 KB)
    float acc = 0.0f;
    #pragma unroll
    for (int i = 0; i < 8; i++) {
        float4 c = __ldg(&g_coeff[lane + 32 * i]);
        float h = fmaf(fa, c.x, fmaf(fb, c.y, c.z));
        h = fmaxf(h, 0.0f);
        acc = fmaf(h, c.w, acc);
    }
    #pragma unroll
    for (int off = 16; off; off >>= 1)
        acc += __shfl_xor_sync(FULL, acc, off);
    acc += g_b2_40;

    int res = ((int)rintf(acc)) & 255;   // rintf == round-half-even == jnp.round
    int e_lo = 80 + (res & 15);
    int e_hi = 96 + (res >> 4);

    int base = lane << 2;
    float* vc = reinterpret_cast<float*>(&v);
    if (e_lo >= base && e_lo < base + 4) vc[e_lo - base] += 2.0f;
    if (e_hi >= base && e_hi < base + 4) vc[e_hi - base] += 2.0f;
}

__global__ void __launch_bounds__(256, 4)
byte_mul_kernel(const float* __restrict__ x,
                float* __restrict__ out,
                int n_tokens)
{
    const unsigned FULL = 0xffffffffu;
    int warp_global = (blockIdx.x * blockDim.x + threadIdx.x) >> 5;
    int lane = threadIdx.x & 31;
    int tok0 = warp_global * 4;
    if (tok0 >= n_tokens) return;
    int nt = n_tokens - tok0; if (nt > 4) nt = 4;

    const float4* __restrict__ xin  = reinterpret_cast<const float4*>(x)   + (size_t)tok0 * 32;
    float4*       __restrict__ yout = reinterpret_cast<float4*>(out)       + (size_t)tok0 * 32;

    // front-batched independent loads: 4 LDG.128 in flight per lane
    float4 v[4];
    #pragma unroll
    for (int t = 0; t < 4; t++)
        if (t < nt) v[t] = xin[t * 32 + lane];

    // lane 0 holds elements 0,1 of every token chunk it loaded -> one broadcast
    int act = 0;
    if (lane == 0) {
        #pragma unroll
        for (int t = 0; t < 4; t++)
            if (t < nt && v[t].x >= 0.5f && v[t].y >= 0.5f) act |= (1 << t);
    }
    act = __shfl_sync(FULL, act, 0);

    if (act) {
        #pragma unroll
        for (int t = 0; t < 4; t++)
            if (act & (1 << t)) process_active(v[t], lane, FULL);
    }

    #pragma unroll
    for (int t = 0; t < 4; t++)
        if (t < nt) yout[t * 32 + lane] = v[t];
}

extern "C" void kernel_launch(void* const* d_in, const int* in_sizes, int n_in,
                              void* d_out, int out_size)
{
    const float* x  = (const float*)d_in[0];  // [8, 8192, 128]
    const float* W1 = (const float*)d_in[1];  // [64, 256]
    const float* b1 = (const float*)d_in[2];  // [256]
    const float* W2 = (const float*)d_in[3];  // [256, 64]
    const float* b2 = (const float*)d_in[4];  // [64]
    float* out = (float*)d_out;

    int n_tokens = in_sizes[0] / 128;         // 65536

    prep_kernel<<<1, 256>>>(W1, b1, W2, b2);

    int tokens_per_block = 4 * 8;             // 4 tokens/warp, 8 warps/block
    int blocks = (n_tokens + tokens_per_block - 1) / tokens_per_block;
    byte_mul_kernel<<<blocks, 256>>>(x, out, n_tokens);
}

// round 8
// speedup vs baseline: 1.0233x; 1.0233x over previous
#include <cuda_runtime.h>
#include <cstdint>

// Layout: MARK_AX=0, OP_MUL=1, ALU_LO=16, ALU_HI=32, AX_CARRY_LO=48, AX_CARRY_HI=64,
// OUTPUT_LO=80, OUTPUT_HI=96, BD_DIM=128. GE pos-0 input is 3-sparse:
//   h_j = relu(a*W1[0,j] + b*W1[1,j] + W1[29,j] + b1[j]),  y = sum_j h_j*W2[j,40] + b2[40]
// Coefficients packed once per launch: g_coeff[j] = (W1[0,j], W1[1,j], W1[29,j]+b1[j], W2[j,40]).
//
// Main kernel: 4 tokens/warp. Copy path = 4 front-batched LDG.128 -> 4 STG.128
// (store depends only on its load). Active tokens are handled AFTER the copy by
// re-reading the (L1-hot) needed elements, so v registers die early (low regs).

__device__ float4 g_coeff[256];
__device__ float  g_b2_40;

__global__ void prep_kernel(const float* __restrict__ W1,
                            const float* __restrict__ b1,
                            const float* __restrict__ W2,
                            const float* __restrict__ b2)
{
    int j = threadIdx.x;  // 256 threads
    g_coeff[j] = make_float4(W1[j],
                             W1[256 + j],
                             W1[29 * 256 + j] + b1[j],
                             W2[j * 64 + 40]);
    if (j == 0) g_b2_40 = b2[40];
}

// Process one active token: argmax segments + MLP + scatter overwrite.
// xtok = x + tok*128 (scalar), otok = out + tok*128 (scalar).
__device__ __forceinline__ void process_active(const float* __restrict__ xtok,
                                               float* __restrict__ otok,
                                               int lane, unsigned FULL)
{
    // Reload the argmax region (elems 16..79 -> lanes 4..19, L1-hot).
    float4 w = make_float4(0.f, 0.f, 0.f, 0.f);
    if (lane >= 4 && lane < 20)
        w = reinterpret_cast<const float4*>(xtok)[lane];

    // local argmax among 4 components (first-max wins: strict >)
    float best = w.x; int bidx = 0;
    if (w.y > best) { best = w.y; bidx = 1; }
    if (w.z > best) { best = w.z; bidx = 2; }
    if (w.w > best) { best = w.w; bidx = 3; }
    int gidx = ((lane & 3) << 2) | bidx;

    // butterfly within aligned lane quads (each quad = one 16-elem segment)
    #pragma unroll
    for (int off = 1; off <= 2; off <<= 1) {
        float ob = __shfl_xor_sync(FULL, best, off);
        int   oi = __shfl_xor_sync(FULL, gidx, off);
        if (ob > best || (ob == best && oi < gidx)) { best = ob; gidx = oi; }
    }

    int a_lo = __shfl_sync(FULL, gidx, 4);    // segment [16,32)
    int a_hi = __shfl_sync(FULL, gidx, 8);    // segment [32,48)
    int b_lo = __shfl_sync(FULL, gidx, 12);   // segment [48,64)
    int b_hi = __shfl_sync(FULL, gidx, 16);   // segment [64,80)

    float fa = (float)(a_lo | (a_hi << 4));
    float fb = (float)(b_lo | (b_hi << 4));

    // MLP from packed coefficients: j = lane + 32*i -> coalesced, L1-hot (4 KB)
    float acc = 0.0f;
    #pragma unroll
    for (int i = 0; i < 8; i++) {
        float4 c = __ldg(&g_coeff[lane + 32 * i]);
        float h = fmaf(fa, c.x, fmaf(fb, c.y, c.z));
        h = fmaxf(h, 0.0f);
        acc = fmaf(h, c.w, acc);
    }
    #pragma unroll
    for (int off = 16; off; off >>= 1)
        acc += __shfl_xor_sync(FULL, acc, off);
    acc += g_b2_40;

    int res = ((int)rintf(acc)) & 255;   // rintf == round-half-even == jnp.round
    int e_lo = 80 + (res & 15);
    int e_hi = 96 + (res >> 4);

    // Scatter: the lane whose STG.128 covered element e overwrites it with x[e]+2.
    // Same-thread ordering (wide store earlier, scalar store later) is guaranteed.
    if ((e_lo >> 2) == lane) otok[e_lo] = xtok[e_lo] + 2.0f;
    if ((e_hi >> 2) == lane) otok[e_hi] = xtok[e_hi] + 2.0f;
}

__global__ void __launch_bounds__(256, 6)
byte_mul_kernel(const float* __restrict__ x,
                float* __restrict__ out,
                int n_tokens)
{
    const unsigned FULL = 0xffffffffu;
    int warp_global = (blockIdx.x * blockDim.x + threadIdx.x) >> 5;
    int lane = threadIdx.x & 31;
    int tok0 = warp_global * 4;
    if (tok0 >= n_tokens) return;

    const float4* __restrict__ xin  = reinterpret_cast<const float4*>(x)   + (size_t)tok0 * 32;
    float4*       __restrict__ yout = reinterpret_cast<float4*>(out)       + (size_t)tok0 * 32;

    bool full4 = (tok0 + 4 <= n_tokens);
    int act = 0;

    if (full4) {
        // front-batched independent loads (MLP=4)
        float4 v0 = xin[      lane];
        float4 v1 = xin[32  + lane];
        float4 v2 = xin[64  + lane];
        float4 v3 = xin[96  + lane];

        // lane 0 holds elems 0,1 of each token -> pack active bits, 1 broadcast
        if (lane == 0) {
            if (v0.x >= 0.5f && v0.y >= 0.5f) act |= 1;
            if (v1.x >= 0.5f && v1.y >= 0.5f) act |= 2;
            if (v2.x >= 0.5f && v2.y >= 0.5f) act |= 4;
            if (v3.x >= 0.5f && v3.y >= 0.5f) act |= 8;
        }
        act = __shfl_sync(FULL, act, 0);

        // unconditional copy; each store depends only on its own load
        yout[      lane] = v0;
        yout[32  + lane] = v1;
        yout[64  + lane] = v2;
        yout[96  + lane] = v3;
    } else {
        int nt = n_tokens - tok0;
        for (int t = 0; t < nt; t++) {
            float4 v = xin[t * 32 + lane];
            int a = 0;
            if (lane == 0 && v.x >= 0.5f && v.y >= 0.5f) a = 1;
            a = __shfl_sync(FULL, a, 0);
            act |= (a << t);
            yout[t * 32 + lane] = v;
        }
    }

    if (!act) return;

    const float* xs = x   + (size_t)tok0 * 128;
    float*       os = out + (size_t)tok0 * 128;
    #pragma unroll
    for (int t = 0; t < 4; t++)
        if (act & (1 << t))
            process_active(xs + t * 128, os + t * 128, lane, FULL);
}

extern "C" void kernel_launch(void* const* d_in, const int* in_sizes, int n_in,
                              void* d_out, int out_size)
{
    const float* x  = (const float*)d_in[0];  // [8, 8192, 128]
    const float* W1 = (const float*)d_in[1];  // [64, 256]
    const float* b1 = (const float*)d_in[2];  // [256]
    const float* W2 = (const float*)d_in[3];  // [256, 64]
    const float* b2 = (const float*)d_in[4];  // [64]
    float* out = (float*)d_out;

    int n_tokens = in_sizes[0] / 128;         // 65536

    prep_kernel<<<1, 256>>>(W1, b1, W2, b2);

    int tokens_per_block = 4 * 8;             // 4 tokens/warp, 8 warps/block
    int blocks = (n_tokens + tokens_per_block - 1) / tokens_per_block;
    byte_mul_kernel<<<blocks, 256>>>(x, out, n_tokens);
}